// round 14
// baseline (speedup 1.0000x reference)
#include <cuda_runtime.h>
#include <cuda_fp16.h>
#include <math.h>
#include <stdint.h>

#define CDIM   512
#define NHEADS 8
#define DH     64
#define NWIN   32
#define SLEN   512
#define MROWS  (NWIN*SLEN)   // 16384

// ------------------------- device scratch (no allocs) -------------------------
__device__ __align__(16) __half g_xh[MROWS*CDIM];          // gathered x, fp16
__device__ __align__(16) __half g_atth[MROWS*CDIM];        // attention out, fp16
__device__ __align__(16) __half g_W[2048*CDIM];            // [n][k]: 0..1535 [Wq|Wk|Wv]^T, 1536..2047 Wo^T
__device__ __align__(16) __half g_Qh[NWIN*NHEADS*SLEN*DH];
__device__ __align__(16) __half g_Kh[NWIN*NHEADS*SLEN*DH];
__device__ __align__(16) __half g_Vt[NWIN*NHEADS*DH*SLEN]; // transposed [nh][d][t]
__device__ float g_tabc[16*SLEN];
__device__ float g_tabs[16*SLEN];

// ------------------------- helpers -------------------------
__device__ __forceinline__ uint32_t smem_u32(const void* p) {
    uint32_t a;
    asm("{ .reg .u64 t; cvta.to.shared.u64 t, %1; cvt.u32.u64 %0, t; }" : "=r"(a) : "l"(p));
    return a;
}
__device__ __forceinline__ void cpasync16(uint32_t dst, const void* src) {
    asm volatile("cp.async.cg.shared.global [%0], [%1], 16;" :: "r"(dst), "l"(src) : "memory");
}
#define CP_COMMIT() asm volatile("cp.async.commit_group;" ::: "memory")
#define CP_WAIT(n)  asm volatile("cp.async.wait_group %0;" :: "n"(n) : "memory")

__device__ __forceinline__ void ldm_x4(uint32_t& r0, uint32_t& r1, uint32_t& r2, uint32_t& r3, uint32_t a) {
    asm volatile("ldmatrix.sync.aligned.m8n8.x4.shared.b16 {%0,%1,%2,%3}, [%4];"
                 : "=r"(r0), "=r"(r1), "=r"(r2), "=r"(r3) : "r"(a));
}
__device__ __forceinline__ void mma16816(float* d, const uint32_t* a, const uint32_t* b) {
    asm volatile(
        "mma.sync.aligned.m16n8k16.row.col.f32.f16.f16.f32 "
        "{%0,%1,%2,%3}, {%4,%5,%6,%7}, {%8,%9}, {%0,%1,%2,%3};"
        : "+f"(d[0]), "+f"(d[1]), "+f"(d[2]), "+f"(d[3])
        : "r"(a[0]), "r"(a[1]), "r"(a[2]), "r"(a[3]), "r"(b[0]), "r"(b[1]));
}
__device__ __forceinline__ uint32_t pack_h(__half a, __half b) {
    return ((uint32_t)__half_as_ushort(b) << 16) | __half_as_ushort(a);
}
// 128B-pitch XOR swizzle (rows of 64 fp16), ch = 16B segment 0..7
__device__ __forceinline__ uint32_t swz128(int r, int ch) {
    return (uint32_t)(r * 128 + ((ch ^ (r & 7)) << 4));
}

// ------------------------- fused prep kernel -------------------------
// blocks [0,4096): x gather->fp16 (2 float4/thread); [4096,8192): W transpose; [8192,8224): rotary table
__global__ __launch_bounds__(256) void prep_all_kernel(
    const float* __restrict__ x,
    const float* __restrict__ Wq, const float* __restrict__ Wk,
    const float* __restrict__ Wv, const float* __restrict__ Wo)
{
    const int gb = blockIdx.x;
    if (gb < 4096) {
        int t2 = (gb * 256 + threadIdx.x) * 2;
#pragma unroll
        for (int u = 0; u < 2; u++) {
            int id4 = t2 + u;
            int m = id4 >> 7;
            int k4 = (id4 & 127) << 2;
            int nwin = m >> 9, s = m & 511;
            int b = nwin & 1, wb = (nwin >> 1) & 3, hb = nwin >> 3;
            int f = s >> 6, r = (s >> 3) & 7, cc = s & 7;
            const float* src = x + (size_t)((((b*8 + f)*32 + hb*8 + r)*32 + wb*8 + cc)) * CDIM + k4;
            float4 v = *(const float4*)src;
            uint2 hv = { pack_h(__float2half_rn(v.x), __float2half_rn(v.y)),
                         pack_h(__float2half_rn(v.z), __float2half_rn(v.w)) };
            *(uint2*)(g_xh + (size_t)m * CDIM + k4) = hv;
        }
    } else if (gb < 8192) {
        int idx = (gb - 4096) * 256 + threadIdx.x;
        int n = idx & 511;
        int km = idx >> 9;
        int mat = km >> 9, k = km & 511;
        const float* W = (mat == 0) ? Wq : (mat == 1) ? Wk : (mat == 2) ? Wv : Wo;
        float v = W[(size_t)k * CDIM + n];
        g_W[(size_t)(mat * 512 + n) * CDIM + k] = __float2half_rn(v);
    } else {
        int idx = (gb - 8192) * 256 + threadIdx.x;
        if (idx < 16 * SLEN) {
            int jj = idx >> 9, s = idx & 511;
            const float LN = 0.5756462732485114210f;    // ln(10000)/16
            float ang = (float)s * expf(-LN * (float)jj);
            float sn, cs;
            sincosf(ang, &sn, &cs);
            g_tabc[idx] = cs;
            g_tabs[idx] = sn;
        }
    }
}

// ------------------------- mma.sync GEMM (3-stage, BK=64, 4 warps, 64x64 warp tiles) -------------------------
#define BM 128
#define BN 128
#define BK 64
#define PLSTG (128*128)       // 16384: one operand tile (128 rows x 128B)
#define STAGE (2*PLSTG)       // 32768
#define SA_OFF(st)  ((st)*STAGE)
#define SB_OFF(st)  ((st)*STAGE + PLSTG)
#define SMEM_TOTAL (3*STAGE)  // 98304 -> 2 CTAs/SM

template<int MODE>
__global__ __launch_bounds__(128) void gemm_kernel(float* __restrict__ out,
                                                   const float* __restrict__ bo)
{
    extern __shared__ char smem[];
    const uint32_t sb = smem_u32(smem);
    const int tid  = threadIdx.x;
    const int lane = tid & 31;
    const int wid  = tid >> 5;       // 0..3
    const int warpM = wid >> 1;      // 0..1 : 64-row slab
    const int warpN = wid & 1;       // 0..1 : 64-col slab
    const int gid = lane >> 2;
    const int tig = lane & 3;
    const int lrow = lane & 15;
    const int lside = lane >> 4;

    const int m0 = blockIdx.y * BM;
    const int n0 = blockIdx.x * BN;
    const int nrow0 = MODE ? (1536 + n0) : n0;
    const __half* Ap = MODE ? g_atth : g_xh;

    float acc[4][8][4];
#pragma unroll
    for (int i = 0; i < 4; i++)
#pragma unroll
        for (int j = 0; j < 8; j++)
#pragma unroll
            for (int t = 0; t < 4; t++) acc[i][j][t] = 0.f;

    auto load_chunk = [&](int c, int st) {
        const int k0 = c * BK;
#pragma unroll
        for (int i = tid; i < 1024; i += 128) {        // A: 128 rows x 8 segs
            int rr = i >> 3, ch = i & 7;
            const __half* src = Ap + (size_t)(m0 + rr) * CDIM + k0 + ch * 8;
            cpasync16(sb + SA_OFF(st) + swz128(rr, ch), src);
        }
#pragma unroll
        for (int i = tid; i < 1024; i += 128) {        // B: 128 rows x 8 segs
            int rr = i >> 3, ch = i & 7;
            const __half* src = g_W + (size_t)(nrow0 + rr) * CDIM + k0 + ch * 8;
            cpasync16(sb + SB_OFF(st) + swz128(rr, ch), src);
        }
        CP_COMMIT();
    };

    load_chunk(0, 0);
    load_chunk(1, 1);

    const int NCH = CDIM / BK;   // 8

    for (int c = 0; c < NCH; c++) {
        if (c == NCH - 1) CP_WAIT(0); else CP_WAIT(1);
        __syncthreads();
        if (c + 2 < NCH) load_chunk(c + 2, (c + 2) % 3);
        const int st = c % 3;
#pragma unroll
        for (int ks = 0; ks < 4; ks++) {                // 4 k16 steps per 64-chunk
            const int chq = ks * 2 + lside;
            uint32_t ah[4][4];
#pragma unroll
            for (int mt = 0; mt < 4; mt++) {
                int ra = warpM*64 + mt*16 + lrow;
                ldm_x4(ah[mt][0], ah[mt][1], ah[mt][2], ah[mt][3],
                       sb + SA_OFF(st) + swz128(ra, chq));
            }
            uint32_t bh[8][2];
#pragma unroll
            for (int ntp = 0; ntp < 4; ntp++) {
                int rb = warpN*64 + ntp*16 + lrow;
                ldm_x4(bh[2*ntp][0], bh[2*ntp+1][0], bh[2*ntp][1], bh[2*ntp+1][1],
                       sb + SB_OFF(st) + swz128(rb, chq));
            }
#pragma unroll
            for (int mt = 0; mt < 4; mt++)
#pragma unroll
                for (int nt = 0; nt < 8; nt++) mma16816(acc[mt][nt], ah[mt], bh[nt]);
        }
    }

    const int mwbase = m0 + warpM * 64;
    const int cwbase = n0 + warpN * 64;

#pragma unroll
    for (int mt = 0; mt < 4; mt++) {
#pragma unroll
        for (int nt = 0; nt < 8; nt++) {
            const int g = cwbase + nt * 8 + tig * 2;
            if (MODE == 0) {
                const int mat = g >> 9;
                const int cc = g & 511;
                const int head = cc >> 6;
                const int d = cc & 63;
#pragma unroll
                for (int half = 0; half < 2; half++) {
                    const int row = mwbase + mt * 16 + gid + half * 8;
                    const int nw = row >> 9;
                    const int s  = row & 511;
                    float v0 = acc[mt][nt][half * 2];
                    float v1 = acc[mt][nt][half * 2 + 1];
                    if (mat < 2 && d < 32) {
                        const int j0 = d >> 1;
                        float cs = g_tabc[j0 * 512 + s];
                        float sn = g_tabs[j0 * 512 + s];
                        float w0 = v0 * cs - v1 * sn;
                        float w1 = v1 * cs + v0 * sn;
                        v0 = w0; v1 = w1;
                    }
                    const int nhh = nw * NHEADS + head;
                    uint32_t hv = pack_h(__float2half_rn(v0), __float2half_rn(v1));
                    if (mat == 0) {
                        *(uint32_t*)(g_Qh + ((size_t)nhh * SLEN + s) * DH + d) = hv;
                    } else if (mat == 1) {
                        *(uint32_t*)(g_Kh + ((size_t)nhh * SLEN + s) * DH + d) = hv;
                    } else {
                        size_t vb = ((size_t)nhh * DH + d) * SLEN + s;
                        g_Vt[vb]        = __float2half_rn(v0);
                        g_Vt[vb + SLEN] = __float2half_rn(v1);
                    }
                }
            } else {
                const float2 bias = *(const float2*)(bo + g);
#pragma unroll
                for (int half = 0; half < 2; half++) {
                    const int row = mwbase + mt * 16 + gid + half * 8;
                    const int nwv = row >> 9, ss = row & 511;
                    const int b = nwv & 1, wb = (nwv >> 1) & 3, hb = nwv >> 3;
                    const int fr = ss >> 6, rr = (ss >> 3) & 7, c2 = ss & 7;
                    const size_t obase = ((size_t)b * (8*32*32) + (size_t)fr * (32*32)
                                        + (size_t)(hb*8 + rr) * 32 + (wb*8 + c2)) * CDIM;
                    float2 v = { acc[mt][nt][half*2] + bias.x,
                                 acc[mt][nt][half*2 + 1] + bias.y };
                    *(float2*)(out + obase + g) = v;
                }
            }
        }
    }
}

// ------------------------- flash attention (fp16 single-plane, unchanged from R13) -------------------------
// smem: Q 16KB | 3 stages x (K 8KB + V 8KB) | P 16KB = 81920 -> 2 CTAs/SM
#define AQ_OFF       0
#define AK_OFF(st)   (16384 + (st) * 16384)
#define AV_OFF(st)   (16384 + (st) * 16384 + 8192)
#define APP_OFF      65536
#define ATTN_SMEM    81920

__global__ __launch_bounds__(256) void attn_kernel()
{
    extern __shared__ char smem[];
    const uint32_t sb = smem_u32(smem);
    const int qt = blockIdx.x;
    const int nh = blockIdx.y;
    const int tid = threadIdx.x;
    const int lane = tid & 31;
    const int wid = tid >> 5;
    const int gid = lane >> 2;
    const int tig = lane & 3;
    const int lrow = lane & 15;
    const int lside = lane >> 4;

    // Q tile (128 x 64), swizzled 128B rows
    {
        const size_t qbase = ((size_t)nh * SLEN + qt * 128) * DH;
#pragma unroll
        for (int i = tid; i < 1024; i += 256) {
            int r = i >> 3, ch = i & 7;
            cpasync16(sb + AQ_OFF + swz128(r, ch), g_Qh + qbase + (size_t)r * DH + ch * 8);
        }
        CP_COMMIT();
    }

    const int nkt = 2 * qt + 2;

    auto load_kv = [&](int kt, int st) {
#pragma unroll
        for (int i = tid; i < 1024; i += 256) {
            if (i < 512) {                        // K tile [t][d]
                int r = i >> 3, ch = i & 7;
                cpasync16(sb + AK_OFF(st) + swz128(r, ch),
                          g_Kh + ((size_t)nh * SLEN + kt * 64 + r) * DH + ch * 8);
            } else {                              // V^T tile [d][t]
                int j = i - 512;
                int r = j >> 3, ch = j & 7;
                cpasync16(sb + AV_OFF(st) + swz128(r, ch),
                          g_Vt + ((size_t)nh * DH + r) * SLEN + kt * 64 + ch * 8);
            }
        }
        CP_COMMIT();
    };

    load_kv(0, 0);
    if (nkt > 1) load_kv(1, 1);

    float accO[8][4];
#pragma unroll
    for (int j = 0; j < 8; j++)
#pragma unroll
        for (int t = 0; t < 4; t++) accO[j][t] = 0.f;
    float lsum0 = 0.f, lsum1 = 0.f;

    const int qrow0 = qt * 128 + wid * 16;

    for (int kt = 0; kt < nkt; kt++) {
        if (kt == nkt - 1) CP_WAIT(0); else CP_WAIT(1);
        __syncthreads();
        if (kt + 2 < nkt) load_kv(kt + 2, (kt + 2) % 3);
        const int st = kt % 3;

        // ---- S = Q K^T ----
        float accS[8][4];
#pragma unroll
        for (int j = 0; j < 8; j++)
#pragma unroll
            for (int t = 0; t < 4; t++) accS[j][t] = 0.f;

#pragma unroll
        for (int k4 = 0; k4 < 4; k4++) {
            const int chq = k4 * 2 + lside;
            uint32_t qh[4];
            ldm_x4(qh[0], qh[1], qh[2], qh[3], sb + AQ_OFF + swz128(wid*16 + lrow, chq));
            uint32_t kh[8][2];
#pragma unroll
            for (int ntp = 0; ntp < 4; ntp++) {
                ldm_x4(kh[2*ntp][0], kh[2*ntp+1][0], kh[2*ntp][1], kh[2*ntp+1][1],
                       sb + AK_OFF(st) + swz128(ntp*16 + lrow, chq));
            }
#pragma unroll
            for (int nt = 0; nt < 8; nt++) mma16816(accS[nt], qh, kh[nt]);
        }

        // ---- exp + causal + l + fp16 P (warp-private rows, swizzled) ----
#pragma unroll
        for (int nt = 0; nt < 8; nt++) {
#pragma unroll
            for (int half = 0; half < 2; half++) {
                const int row = qrow0 + gid + half * 8;
                const int col0 = kt * 64 + nt * 8 + tig * 2;
                float s0 = accS[nt][half*2]     * 0.125f;
                float s1 = accS[nt][half*2 + 1] * 0.125f;
                float p0 = (col0     <= row) ? __expf(s0) : 0.f;
                float p1 = (col0 + 1 <= row) ? __expf(s1) : 0.f;
                if (half) lsum1 += p0 + p1; else lsum0 += p0 + p1;
                const int r = wid*16 + gid + half*8;
                uint32_t off = (uint32_t)(r * 128 + ((nt ^ (r & 7)) << 4) + tig * 4);
                *(uint32_t*)(smem + APP_OFF + off) =
                    pack_h(__float2half_rn(p0), __float2half_rn(p1));
            }
        }
        __syncwarp();   // P rows are warp-private

        // ---- O += P V ----
#pragma unroll
        for (int k4 = 0; k4 < 4; k4++) {
            const int chq = k4 * 2 + lside;
            uint32_t ph[4];
            ldm_x4(ph[0], ph[1], ph[2], ph[3], sb + APP_OFF + swz128(wid*16 + lrow, chq));
            uint32_t vh[8][2];
#pragma unroll
            for (int ntp = 0; ntp < 4; ntp++) {
                ldm_x4(vh[2*ntp][0], vh[2*ntp+1][0], vh[2*ntp][1], vh[2*ntp+1][1],
                       sb + AV_OFF(st) + swz128(ntp*16 + lrow, chq));
            }
#pragma unroll
            for (int nt = 0; nt < 8; nt++) mma16816(accO[nt], ph, vh[nt]);
        }
    }

    // ---- finalize ----
    lsum0 += __shfl_xor_sync(0xFFFFFFFF, lsum0, 1);
    lsum0 += __shfl_xor_sync(0xFFFFFFFF, lsum0, 2);
    lsum1 += __shfl_xor_sync(0xFFFFFFFF, lsum1, 1);
    lsum1 += __shfl_xor_sync(0xFFFFFFFF, lsum1, 2);
    const float inv0 = 1.f / lsum0;
    const float inv1 = 1.f / lsum1;

    const int nwn = nh >> 3, hh = nh & 7;
#pragma unroll
    for (int half = 0; half < 2; half++) {
        const int srow = qrow0 + gid + half * 8;
        const float inv = half ? inv1 : inv0;
        const size_t mrow = (size_t)nwn * SLEN + srow;
#pragma unroll
        for (int nt = 0; nt < 8; nt++) {
            const int d = nt * 8 + tig * 2;
            float v0 = accO[nt][half*2]     * inv;
            float v1 = accO[nt][half*2 + 1] * inv;
            size_t base = mrow * CDIM + hh * DH + d;
            *(uint32_t*)(g_atth + base) = pack_h(__float2half_rn(v0), __float2half_rn(v1));
        }
    }
}

// ------------------------- launch -------------------------
extern "C" void kernel_launch(void* const* d_in, const int* in_sizes, int n_in,
                              void* d_out, int out_size)
{
    const float* x  = (const float*)d_in[0];
    const float* Wq = (const float*)d_in[1];
    const float* Wk = (const float*)d_in[2];
    const float* Wv = (const float*)d_in[3];
    const float* Wo = (const float*)d_in[4];
    const float* bo = (const float*)d_in[5];
    float* out = (float*)d_out;
    (void)in_sizes; (void)n_in; (void)out_size;

    static bool attr_done = false;
    if (!attr_done) {
        cudaFuncSetAttribute(gemm_kernel<0>, cudaFuncAttributeMaxDynamicSharedMemorySize, SMEM_TOTAL);
        cudaFuncSetAttribute(gemm_kernel<1>, cudaFuncAttributeMaxDynamicSharedMemorySize, SMEM_TOTAL);
        cudaFuncSetAttribute(attn_kernel, cudaFuncAttributeMaxDynamicSharedMemorySize, ATTN_SMEM);
        attr_done = true;
    }

    prep_all_kernel<<<8224, 256>>>(x, Wq, Wk, Wv, Wo);

    dim3 gq(12, MROWS / BM);             // N=1536
    gemm_kernel<0><<<gq, 128, SMEM_TOTAL>>>(nullptr, nullptr);

    dim3 ga(4, NWIN * NHEADS);
    attn_kernel<<<ga, 256, ATTN_SMEM>>>();

    dim3 go(4, MROWS / BM);              // N=512
    gemm_kernel<1><<<go, 128, SMEM_TOTAL>>>(out, bo);
}